// round 2
// baseline (speedup 1.0000x reference)
#include <cuda_runtime.h>
#include <cstdint>

// Problem constants (from reference): B=64, R=32, N=16384, D=64, O=8
#define PB 64
#define PR 32
#define PN 16384
#define PD 64
#define PO 8

// Scratch (allocation-free rule: __device__ globals)
__device__ float g_s[PB][PD];   // sum over valid n of l2-normalized h_context rows
__device__ float g_cnt[PB];     // nvalid per b

// ---------------------------------------------------------------------------
// Kernel 1: zero the scratch
// ---------------------------------------------------------------------------
__global__ void ssfw_zero_kernel() {
    int i = blockIdx.x * blockDim.x + threadIdx.x;
    if (i < PB * PD) ((float*)g_s)[i] = 0.0f;
    if (i < PB) g_cnt[i] = 0.0f;
}

// ---------------------------------------------------------------------------
// Kernel 2: sparse masked accumulation of normalized context rows.
// Grid: (chunksPerB, B), block 256 threads = 8 warps.
// Each warp owns a contiguous slice of rows of one b.
// Per 32-row group: coalesced per-lane validity check -> ballot -> the warp
// cooperatively normalizes+accumulates only the valid rows (~0.74%).
// Masks arrive as int32 (harness encodes bool as int32; nonzero test also
// covers a float32 encoding bit-pattern).
// ---------------------------------------------------------------------------
__global__ void ssfw_accum_kernel(const float* __restrict__ h_context,
                                  const int* __restrict__ center_o,
                                  const int* __restrict__ o_types,
                                  const int* __restrict__ adj_mask,
                                  const int* __restrict__ two_hop_mask) {
    const int b    = blockIdx.y;
    const int lane = threadIdx.x & 31;
    const int warp = threadIdx.x >> 5;
    const int warpsPerB   = gridDim.x * (blockDim.x >> 5);
    const int gwarp       = blockIdx.x * (blockDim.x >> 5) + warp;
    const int rowsPerWarp = PN / warpsPerB;
    const int rowStart    = gwarp * rowsPerWarp;

    const int cb = center_o[b];
    const size_t maskBase = (size_t)b * PN;

    float accx = 0.0f, accy = 0.0f;
    int   cnt  = 0;

    for (int base = rowStart; base < rowStart + rowsPerWarp; base += 32) {
        const size_t idx = maskBase + base + lane;
        // coalesced loads: 32 consecutive int32 each
        const bool hop   = (adj_mask[idx] != 0) | (two_hop_mask[idx] != 0);
        const bool valid = hop && (o_types[idx] == cb);
        cnt += valid ? 1 : 0;

        unsigned m = __ballot_sync(0xffffffffu, valid);
        while (m) {
            const int j = __ffs(m) - 1;
            m &= (m - 1);
            const int row = base + j;
            // whole warp loads this 256B row: lane -> float2 slice (coalesced)
            const float2 v =
                ((const float2*)(h_context + ((size_t)b * PN + row) * PD))[lane];
            float ss = v.x * v.x + v.y * v.y;
            #pragma unroll
            for (int o = 16; o; o >>= 1)
                ss += __shfl_xor_sync(0xffffffffu, ss, o);
            const float inv = rsqrtf(fmaxf(ss, 1e-12f));
            accx += v.x * inv;
            accy += v.y * inv;
        }
    }

    // 64 global float atomics per warp (2048 warps total — negligible)
    atomicAdd(&g_s[b][2 * lane],     accx);
    atomicAdd(&g_s[b][2 * lane + 1], accy);

    #pragma unroll
    for (int o = 16; o; o >>= 1)
        cnt += __shfl_xor_sync(0xffffffffu, cnt, o);
    if (lane == 0) atomicAdd(&g_cnt[b], (float)cnt);
}

// ---------------------------------------------------------------------------
// Kernel 3: finalize. One warp per (b, r).
// w = relu(lambda_so[r, center_o[b]] / max(cnt,1)) * (1 - (norm_l . s) / max(cnt,1e-9))
// ---------------------------------------------------------------------------
__global__ void ssfw_finalize_kernel(const float* __restrict__ l_local,
                                     const float* __restrict__ lambda_so,
                                     const int* __restrict__ center_o,
                                     float* __restrict__ out) {
    const int gwarp = (blockIdx.x * blockDim.x + threadIdx.x) >> 5;
    const int lane  = threadIdx.x & 31;
    if (gwarp >= PB * PR) return;
    const int b = gwarp / PR;
    const int r = gwarp % PR;

    const float2 v =
        ((const float2*)(l_local + ((size_t)b * PR + r) * PD))[lane];
    const float sx = g_s[b][2 * lane];
    const float sy = g_s[b][2 * lane + 1];

    float ss  = v.x * v.x + v.y * v.y;
    float dot = v.x * sx + v.y * sy;
    #pragma unroll
    for (int o = 16; o; o >>= 1) {
        ss  += __shfl_xor_sync(0xffffffffu, ss,  o);
        dot += __shfl_xor_sync(0xffffffffu, dot, o);
    }

    if (lane == 0) {
        const float cntf = g_cnt[b];
        const float inv  = rsqrtf(fmaxf(ss, 1e-12f));
        const float avg  = (dot * inv) / fmaxf(cntf, 1e-9f);
        const float lam  = lambda_so[r * PO + center_o[b]];
        const float w    = fmaxf(lam / fmaxf(cntf, 1.0f), 0.0f) * (1.0f - avg);
        out[b * PR + r] = w;
    }
}

// ---------------------------------------------------------------------------
// Launch
// Input order (setup_inputs): l_local, h_context, lambda_so, center_o,
//                             o_types, adj_mask, two_hop_mask
// ---------------------------------------------------------------------------
extern "C" void kernel_launch(void* const* d_in, const int* in_sizes, int n_in,
                              void* d_out, int out_size) {
    const float* l_local   = (const float*)d_in[0];
    const float* h_context = (const float*)d_in[1];
    const float* lambda_so = (const float*)d_in[2];
    const int*   center_o  = (const int*)d_in[3];
    const int*   o_types   = (const int*)d_in[4];
    const int*   adj_mask  = (const int*)d_in[5];
    const int*   two_hop   = (const int*)d_in[6];
    float*       out       = (float*)d_out;

    ssfw_zero_kernel<<<(PB * PD + 255) / 256, 256>>>();

    // 4 blocks/b x 8 warps = 32 warps per b; each warp covers 512 rows
    dim3 grid_acc(4, PB);
    ssfw_accum_kernel<<<grid_acc, 256>>>(h_context, center_o, o_types,
                                         adj_mask, two_hop);

    // one warp per (b,r): 2048 warps = 65536 threads = 256 blocks
    ssfw_finalize_kernel<<<(PB * PR * 32) / 256, 256>>>(l_local, lambda_so,
                                                        center_o, out);
}

// round 3
// speedup vs baseline: 1.4858x; 1.4858x over previous
#include <cuda_runtime.h>
#include <cstdint>

// Problem constants (from reference): B=64, R=32, N=16384, D=64, O=8
#define PB 64
#define PR 32
#define PN 16384
#define PD 64
#define PO 8

// ---------------------------------------------------------------------------
// Fully fused kernel: one block per b, 1024 threads (32 warps).
//
// Phase 1 (per warp, 512 contiguous rows): coalesced validity scan of
//   o_types / adj_mask / two_hop_mask (int32 each), ballot-compacted gather of
//   valid h_context rows (~0.74%), warp-level L2 normalize, accumulate into
//   per-thread registers, then smem atomics into s[64] + count.
// Phase 2 (after one __syncthreads): warp w handles output r=w:
//   normalize l_local[b][r], dot with s, apply scalar epilogue, write out.
// ---------------------------------------------------------------------------
__global__ __launch_bounds__(1024, 1)
void ssfw_fused_kernel(const float* __restrict__ l_local,
                       const float* __restrict__ h_context,
                       const float* __restrict__ lambda_so,
                       const int* __restrict__ center_o,
                       const int* __restrict__ o_types,
                       const int* __restrict__ adj_mask,
                       const int* __restrict__ two_hop_mask,
                       float* __restrict__ out) {
    __shared__ float s[PD];
    __shared__ float scnt;

    const int b    = blockIdx.x;
    const int lane = threadIdx.x & 31;
    const int warp = threadIdx.x >> 5;   // 0..31

    if (threadIdx.x < PD) s[threadIdx.x] = 0.0f;
    if (threadIdx.x == 0) scnt = 0.0f;
    __syncthreads();

    const int cb = center_o[b];
    const size_t maskBase = (size_t)b * PN;

    // ---- Phase 1: masked sparse accumulation ----
    const int rowsPerWarp = PN / 32;          // 512
    const int rowStart    = warp * rowsPerWarp;

    float accx = 0.0f, accy = 0.0f;
    int   cnt  = 0;

    #pragma unroll 4
    for (int base = rowStart; base < rowStart + rowsPerWarp; base += 32) {
        const size_t idx = maskBase + base + lane;
        // three coalesced int32 streams
        const bool hop   = (adj_mask[idx] != 0) | (two_hop_mask[idx] != 0);
        const bool valid = hop && (o_types[idx] == cb);
        cnt += valid ? 1 : 0;

        unsigned m = __ballot_sync(0xffffffffu, valid);
        while (m) {
            const int j = __ffs(m) - 1;
            m &= (m - 1);
            const int row = base + j;
            // warp cooperatively loads this 256B row: lane -> float2 slice
            const float2 v =
                ((const float2*)(h_context + ((size_t)b * PN + row) * PD))[lane];
            float ss = v.x * v.x + v.y * v.y;
            #pragma unroll
            for (int o = 16; o; o >>= 1)
                ss += __shfl_xor_sync(0xffffffffu, ss, o);
            const float inv = rsqrtf(fmaxf(ss, 1e-12f));
            accx += v.x * inv;
            accy += v.y * inv;
        }
    }

    // shared-memory reduction across the 32 warps
    atomicAdd(&s[2 * lane],     accx);
    atomicAdd(&s[2 * lane + 1], accy);
    #pragma unroll
    for (int o = 16; o; o >>= 1)
        cnt += __shfl_xor_sync(0xffffffffu, cnt, o);
    if (lane == 0) atomicAdd(&scnt, (float)cnt);

    __syncthreads();

    // ---- Phase 2: finalize. Warp w computes output r = w ----
    const int r = warp;
    const float2 v =
        ((const float2*)(l_local + ((size_t)b * PR + r) * PD))[lane];
    const float sx = s[2 * lane];
    const float sy = s[2 * lane + 1];

    float ss  = v.x * v.x + v.y * v.y;
    float dot = v.x * sx + v.y * sy;
    #pragma unroll
    for (int o = 16; o; o >>= 1) {
        ss  += __shfl_xor_sync(0xffffffffu, ss,  o);
        dot += __shfl_xor_sync(0xffffffffu, dot, o);
    }

    if (lane == 0) {
        const float cntf = scnt;
        const float inv  = rsqrtf(fmaxf(ss, 1e-12f));
        const float avg  = (dot * inv) / fmaxf(cntf, 1e-9f);
        const float lam  = lambda_so[r * PO + cb];
        const float w    = fmaxf(lam / fmaxf(cntf, 1.0f), 0.0f) * (1.0f - avg);
        out[b * PR + r] = w;
    }
}

// ---------------------------------------------------------------------------
// Launch
// Input order (setup_inputs): l_local, h_context, lambda_so, center_o,
//                             o_types, adj_mask, two_hop_mask
// ---------------------------------------------------------------------------
extern "C" void kernel_launch(void* const* d_in, const int* in_sizes, int n_in,
                              void* d_out, int out_size) {
    const float* l_local   = (const float*)d_in[0];
    const float* h_context = (const float*)d_in[1];
    const float* lambda_so = (const float*)d_in[2];
    const int*   center_o  = (const int*)d_in[3];
    const int*   o_types   = (const int*)d_in[4];
    const int*   adj_mask  = (const int*)d_in[5];
    const int*   two_hop   = (const int*)d_in[6];
    float*       out       = (float*)d_out;

    ssfw_fused_kernel<<<PB, 1024>>>(l_local, h_context, lambda_so, center_o,
                                    o_types, adj_mask, two_hop, out);
}

// round 4
// speedup vs baseline: 2.3304x; 1.5685x over previous
#include <cuda_runtime.h>
#include <cstdint>

// Problem constants: B=64, R=32, N=16384, D=64, O=8
#define PB 64
#define PR 32
#define PN 16384
#define PD 64
#define PO 8

#define BLOCKS_PER_B 8
#define THREADS 256          // 8 warps
#define WARPS (THREADS / 32)

// Global scratch (__device__ globals are zero-initialized at module load;
// the finalizing block resets them to zero each run -> replay-deterministic).
__device__ float        g_s[PB][PD];
__device__ float        g_cnt[PB];
__device__ unsigned int g_ticket[PB];

// ---------------------------------------------------------------------------
// One kernel, grid (BLOCKS_PER_B, PB). Each block scans PN/BLOCKS_PER_B rows
// of one b with int4 (LDG.128) mask loads, ballot-compacts the ~0.74% valid
// rows, L2-normalizes + accumulates them, reduces block-locally in smem, then
// global-atomically into g_s. The last block per b (ticket) finalizes the 32
// outputs and resets the scratch.
// ---------------------------------------------------------------------------
__global__ __launch_bounds__(THREADS)
void ssfw_fused_kernel(const float* __restrict__ l_local,
                       const float* __restrict__ h_context,
                       const float* __restrict__ lambda_so,
                       const int* __restrict__ center_o,
                       const int* __restrict__ o_types,
                       const int* __restrict__ adj_mask,
                       const int* __restrict__ two_hop_mask,
                       float* __restrict__ out) {
    __shared__ float s[PD];
    __shared__ float scnt;
    __shared__ int   sIsLast;

    const int b    = blockIdx.y;
    const int lane = threadIdx.x & 31;
    const int warp = threadIdx.x >> 5;

    if (threadIdx.x < PD) s[threadIdx.x] = 0.0f;
    if (threadIdx.x == 0) scnt = 0.0f;
    __syncthreads();

    const int cb = center_o[b];

    // ---- Phase 1: masked sparse accumulation ----
    // Block covers rows [blockIdx.x*2048, +2048); warp covers 256 rows;
    // per iteration a warp covers 128 rows (int4 per lane), 2 iterations.
    const int rowsPerBlock = PN / BLOCKS_PER_B;            // 2048
    const int rowsPerWarp  = rowsPerBlock / WARPS;         // 256
    const int rowStart     = blockIdx.x * rowsPerBlock + warp * rowsPerWarp;

    const int4* ot4 = (const int4*)(o_types      + (size_t)b * PN);
    const int4* am4 = (const int4*)(adj_mask     + (size_t)b * PN);
    const int4* th4 = (const int4*)(two_hop_mask + (size_t)b * PN);

    float accx = 0.0f, accy = 0.0f;
    int   cnt  = 0;

    #pragma unroll
    for (int it = 0; it < rowsPerWarp / 128; ++it) {
        const int base = rowStart + it * 128;          // 128 rows this iter
        const int vec  = (base >> 2) + lane;           // int4 index
        const int4 ot = __ldg(&ot4[vec]);
        const int4 am = __ldg(&am4[vec]);
        const int4 th = __ldg(&th4[vec]);

        const bool v0 = ((am.x | th.x) != 0) && (ot.x == cb);
        const bool v1 = ((am.y | th.y) != 0) && (ot.y == cb);
        const bool v2 = ((am.z | th.z) != 0) && (ot.z == cb);
        const bool v3 = ((am.w | th.w) != 0) && (ot.w == cb);
        cnt += (int)v0 + (int)v1 + (int)v2 + (int)v3;

        #pragma unroll
        for (int t = 0; t < 4; ++t) {
            const bool vt = (t == 0) ? v0 : (t == 1) ? v1 : (t == 2) ? v2 : v3;
            unsigned m = __ballot_sync(0xffffffffu, vt);
            while (m) {
                const int j = __ffs(m) - 1;
                m &= (m - 1);
                const int row = base + 4 * j + t;
                // warp cooperatively loads this 256B row: lane -> float2 slice
                const float2 v =
                    ((const float2*)(h_context + ((size_t)b * PN + row) * PD))[lane];
                float ss = v.x * v.x + v.y * v.y;
                #pragma unroll
                for (int o = 16; o; o >>= 1)
                    ss += __shfl_xor_sync(0xffffffffu, ss, o);
                const float inv = rsqrtf(fmaxf(ss, 1e-12f));
                accx += v.x * inv;
                accy += v.y * inv;
            }
        }
    }

    // block-local reduction into smem
    atomicAdd(&s[2 * lane],     accx);
    atomicAdd(&s[2 * lane + 1], accy);
    #pragma unroll
    for (int o = 16; o; o >>= 1)
        cnt += __shfl_xor_sync(0xffffffffu, cnt, o);
    if (lane == 0) atomicAdd(&scnt, (float)cnt);
    __syncthreads();

    // one warp pushes the block partial to global scratch
    if (warp == 0) {
        atomicAdd(&g_s[b][2 * lane],     s[2 * lane]);
        atomicAdd(&g_s[b][2 * lane + 1], s[2 * lane + 1]);
        if (lane == 0) atomicAdd(&g_cnt[b], scnt);
    }
    __threadfence();
    __syncthreads();

    if (threadIdx.x == 0) {
        const unsigned old = atomicAdd(&g_ticket[b], 1u);
        sIsLast = (old == BLOCKS_PER_B - 1);
    }
    __syncthreads();
    if (!sIsLast) return;

    // ---- Phase 2 (last block per b): finalize 32 outputs ----
    __threadfence();   // acquire side of the ticket handshake
    const float cntf = g_cnt[b];
    const float invc9 = 1.0f / fmaxf(cntf, 1e-9f);
    const float invc1 = 1.0f / fmaxf(cntf, 1.0f);

    const float sx = g_s[b][2 * lane];
    const float sy = g_s[b][2 * lane + 1];

    #pragma unroll
    for (int rr = 0; rr < PR / WARPS; ++rr) {          // 4 rows per warp
        const int r = warp + rr * WARPS;
        const float2 v =
            ((const float2*)(l_local + ((size_t)b * PR + r) * PD))[lane];
        float ss  = v.x * v.x + v.y * v.y;
        float dot = v.x * sx + v.y * sy;
        #pragma unroll
        for (int o = 16; o; o >>= 1) {
            ss  += __shfl_xor_sync(0xffffffffu, ss,  o);
            dot += __shfl_xor_sync(0xffffffffu, dot, o);
        }
        if (lane == 0) {
            const float inv = rsqrtf(fmaxf(ss, 1e-12f));
            const float avg = dot * inv * invc9;
            const float lam = lambda_so[r * PO + cb];
            out[b * PR + r] = fmaxf(lam * invc1, 0.0f) * (1.0f - avg);
        }
    }

    // ---- reset scratch for the next (graph-replayed) run ----
    __syncthreads();
    if (threadIdx.x < PD) g_s[b][threadIdx.x] = 0.0f;
    if (threadIdx.x == 0) { g_cnt[b] = 0.0f; g_ticket[b] = 0u; }
}

// ---------------------------------------------------------------------------
// Launch. Input order: l_local, h_context, lambda_so, center_o, o_types,
//                      adj_mask, two_hop_mask
// ---------------------------------------------------------------------------
extern "C" void kernel_launch(void* const* d_in, const int* in_sizes, int n_in,
                              void* d_out, int out_size) {
    const float* l_local   = (const float*)d_in[0];
    const float* h_context = (const float*)d_in[1];
    const float* lambda_so = (const float*)d_in[2];
    const int*   center_o  = (const int*)d_in[3];
    const int*   o_types   = (const int*)d_in[4];
    const int*   adj_mask  = (const int*)d_in[5];
    const int*   two_hop   = (const int*)d_in[6];
    float*       out       = (float*)d_out;

    dim3 grid(BLOCKS_PER_B, PB);
    ssfw_fused_kernel<<<grid, THREADS>>>(l_local, h_context, lambda_so,
                                         center_o, o_types, adj_mask, two_hop,
                                         out);
}